// round 1
// baseline (speedup 1.0000x reference)
#include <cuda_runtime.h>
#include <cuda_bf16.h>

// Scratch for the affine-composition tree (no allocations allowed -> device globals).
__device__ float g_M1[100 * 100];  // level-1: 100 chunk matrices (10x10 each)
__device__ float g_c1[100 * 10];
__device__ float g_M2[10 * 100];   // level-2: 10 chunk matrices
__device__ float g_c2[10 * 10];
__device__ float g_M3[100];        // final composed matrix M (row-major [out][in])
__device__ float g_c3[10];         // final composed bias

// Fold PER consecutive affine maps (h -> h*W^T + b) into one.
// Combine rule: applying (M,c) then layer (Wn,bn):
//   M' = Wn @ M        (M'[o][i] = sum_k Wn[o][k] * M[k][i])
//   c' = Wn @ c + bn
template <int PER>
__global__ void fold_kernel(const float* __restrict__ Min, const float* __restrict__ cin,
                            float* __restrict__ Mout, float* __restrict__ cout) {
    __shared__ float In[PER * 100];
    __shared__ float cIn[PER * 10];
    __shared__ float M[100];
    __shared__ float c[10];

    const int b   = blockIdx.x;
    const int tid = threadIdx.x;

    const float* mb = Min + (size_t)b * PER * 100;
    const float* cb = cin + (size_t)b * PER * 10;
    for (int idx = tid; idx < PER * 100; idx += blockDim.x) In[idx] = mb[idx];
    for (int idx = tid; idx < PER * 10; idx += blockDim.x) cIn[idx] = cb[idx];
    __syncthreads();

    if (tid < 100) M[tid] = In[tid];
    if (tid < 10)  c[tid] = cIn[tid];
    __syncthreads();

    const int i = tid / 10;
    const int j = tid % 10;

    #pragma unroll 1
    for (int l = 1; l < PER; ++l) {
        float nm = 0.f, nc = 0.f;
        if (tid < 100) {
            const float* Wn = &In[l * 100];
            #pragma unroll
            for (int k = 0; k < 10; ++k) nm += Wn[i * 10 + k] * M[k * 10 + j];
        }
        if (tid < 10) {
            const float* Wn = &In[l * 100];
            nc = cIn[l * 10 + tid];
            #pragma unroll
            for (int k = 0; k < 10; ++k) nc += Wn[tid * 10 + k] * c[k];
        }
        __syncthreads();
        if (tid < 100) M[tid] = nm;
        if (tid < 10)  c[tid] = nc;
        __syncthreads();
    }

    if (tid < 100) Mout[b * 100 + tid] = M[tid];
    if (tid < 10)  cout[b * 10 + tid]  = c[tid];
}

// Streaming apply: out[r] = x[r] @ M^T + c. Two rows (= 80B = 5 float4) per iter.
__global__ void __launch_bounds__(128) apply_kernel(const float* __restrict__ x,
                                                    float* __restrict__ out,
                                                    long long rows) {
    // Hoist M and c into registers (constant-indexed fully-unrolled accesses).
    float m[100], cc[10];
    #pragma unroll
    for (int t = 0; t < 100; ++t) m[t] = __ldg(&g_M3[t]);
    #pragma unroll
    for (int t = 0; t < 10; ++t) cc[t] = __ldg(&g_c3[t]);

    const long long stride = (long long)gridDim.x * blockDim.x;
    const long long tid    = (long long)blockIdx.x * blockDim.x + threadIdx.x;
    const long long pairs  = rows >> 1;

    for (long long p = tid; p < pairs; p += stride) {
        const float4* xp = (const float4*)(x + p * 20);  // p*80 bytes, 16B-aligned
        float4 v0 = xp[0], v1 = xp[1], v2 = xp[2], v3 = xp[3], v4 = xp[4];

        float h0[10], h1[10];
        h0[0] = v0.x; h0[1] = v0.y; h0[2] = v0.z; h0[3] = v0.w;
        h0[4] = v1.x; h0[5] = v1.y; h0[6] = v1.z; h0[7] = v1.w;
        h0[8] = v2.x; h0[9] = v2.y;
        h1[0] = v2.z; h1[1] = v2.w;
        h1[2] = v3.x; h1[3] = v3.y; h1[4] = v3.z; h1[5] = v3.w;
        h1[6] = v4.x; h1[7] = v4.y; h1[8] = v4.z; h1[9] = v4.w;

        float o0[10], o1[10];
        #pragma unroll
        for (int j = 0; j < 10; ++j) {
            float a = cc[j], bsum = cc[j];
            #pragma unroll
            for (int k = 0; k < 10; ++k) {
                a    += h0[k] * m[j * 10 + k];
                bsum += h1[k] * m[j * 10 + k];
            }
            o0[j] = a;
            o1[j] = bsum;
        }

        float4* op = (float4*)(out + p * 20);
        float4 s0, s1, s2, s3, s4;
        s0.x = o0[0]; s0.y = o0[1]; s0.z = o0[2]; s0.w = o0[3];
        s1.x = o0[4]; s1.y = o0[5]; s1.z = o0[6]; s1.w = o0[7];
        s2.x = o0[8]; s2.y = o0[9]; s2.z = o1[0]; s2.w = o1[1];
        s3.x = o1[2]; s3.y = o1[3]; s3.z = o1[4]; s3.w = o1[5];
        s4.x = o1[6]; s4.y = o1[7]; s4.z = o1[8]; s4.w = o1[9];
        op[0] = s0; op[1] = s1; op[2] = s2; op[3] = s3; op[4] = s4;
    }

    // Odd-row tail (BATCH is even, but stay safe).
    for (long long r = pairs * 2 + tid; r < rows; r += stride) {
        const float* xr = x + r * 10;
        float h[10];
        #pragma unroll
        for (int k = 0; k < 10; ++k) h[k] = xr[k];
        float* orow = out + r * 10;
        #pragma unroll
        for (int j = 0; j < 10; ++j) {
            float a = cc[j];
            #pragma unroll
            for (int k = 0; k < 10; ++k) a += h[k] * m[j * 10 + k];
            orow[j] = a;
        }
    }
}

extern "C" void kernel_launch(void* const* d_in, const int* in_sizes, int n_in,
                              void* d_out, int out_size) {
    // Identify inputs robustly by element count: x=BATCH*10, Ws=1000*100, bs=1000*10.
    const float* x  = nullptr;
    const float* Ws = nullptr;
    const float* bs = nullptr;
    long long x_elems = 0;
    for (int i = 0; i < n_in; ++i) {
        if (in_sizes[i] == 1000 * 100) {
            Ws = (const float*)d_in[i];
        } else if (in_sizes[i] == 1000 * 10) {
            bs = (const float*)d_in[i];
        } else {
            x = (const float*)d_in[i];
            x_elems = in_sizes[i];
        }
    }
    const long long rows = x_elems / 10;

    float *M1, *c1, *M2, *c2, *M3, *c3;
    cudaGetSymbolAddress((void**)&M1, g_M1);
    cudaGetSymbolAddress((void**)&c1, g_c1);
    cudaGetSymbolAddress((void**)&M2, g_M2);
    cudaGetSymbolAddress((void**)&c2, g_c2);
    cudaGetSymbolAddress((void**)&M3, g_M3);
    cudaGetSymbolAddress((void**)&c3, g_c3);

    // Compose 1000 affines -> 1 affine via 3-level tree (10 each).
    fold_kernel<10><<<100, 128>>>(Ws, bs, M1, c1);
    fold_kernel<10><<<10, 128>>>(M1, c1, M2, c2);
    fold_kernel<10><<<1, 128>>>(M2, c2, M3, c3);

    // Streaming apply, persistent grid (~3 CTAs/SM at ~160 regs/thread).
    apply_kernel<<<444, 128>>>(x, (float*)d_out, rows);
}

// round 2
// speedup vs baseline: 1.0065x; 1.0065x over previous
#include <cuda_runtime.h>
#include <cuda_bf16.h>

// Scratch for the affine-composition tree (no allocations allowed -> device globals).
__device__ float g_M1[100 * 100];  // level-1: 100 chunk matrices (10x10 each)
__device__ float g_c1[100 * 10];
__device__ float g_M2[10 * 100];   // level-2: 10 chunk matrices
__device__ float g_c2[10 * 10];
__device__ float g_M3[100];        // final composed matrix M (row-major [out][in])
__device__ float g_c3[10];         // final composed bias

// Fold PER consecutive affine maps (h -> h*W^T + b) into one.
// Combine rule: applying (M,c) then layer (Wn,bn):
//   M' = Wn @ M        (M'[o][i] = sum_k Wn[o][k] * M[k][i])
//   c' = Wn @ c + bn
template <int PER>
__global__ void fold_kernel(const float* __restrict__ Min, const float* __restrict__ cin,
                            float* __restrict__ Mout, float* __restrict__ cout) {
    __shared__ float In[PER * 100];
    __shared__ float cIn[PER * 10];
    __shared__ float M[100];
    __shared__ float c[10];

    const int b   = blockIdx.x;
    const int tid = threadIdx.x;

    const float* mb = Min + (size_t)b * PER * 100;
    const float* cb = cin + (size_t)b * PER * 10;
    for (int idx = tid; idx < PER * 100; idx += blockDim.x) In[idx] = mb[idx];
    for (int idx = tid; idx < PER * 10; idx += blockDim.x) cIn[idx] = cb[idx];
    __syncthreads();

    if (tid < 100) M[tid] = In[tid];
    if (tid < 10)  c[tid] = cIn[tid];
    __syncthreads();

    const int i = tid / 10;
    const int j = tid % 10;

    #pragma unroll 1
    for (int l = 1; l < PER; ++l) {
        float nm = 0.f, nc = 0.f;
        if (tid < 100) {
            const float* Wn = &In[l * 100];
            #pragma unroll
            for (int k = 0; k < 10; ++k) nm += Wn[i * 10 + k] * M[k * 10 + j];
        }
        if (tid < 10) {
            const float* Wn = &In[l * 100];
            nc = cIn[l * 10 + tid];
            #pragma unroll
            for (int k = 0; k < 10; ++k) nc += Wn[tid * 10 + k] * c[k];
        }
        __syncthreads();
        if (tid < 100) M[tid] = nm;
        if (tid < 10)  c[tid] = nc;
        __syncthreads();
    }

    if (tid < 100) Mout[b * 100 + tid] = M[tid];
    if (tid < 10)  cout[b * 10 + tid]  = c[tid];
}

// Streaming apply: out[r] = x[r] @ M^T + c. Two rows (= 80B = 5 float4) per iter.
__global__ void __launch_bounds__(128) apply_kernel(const float* __restrict__ x,
                                                    float* __restrict__ out,
                                                    long long rows) {
    // Hoist M and c into registers (constant-indexed fully-unrolled accesses).
    float m[100], cc[10];
    #pragma unroll
    for (int t = 0; t < 100; ++t) m[t] = __ldg(&g_M3[t]);
    #pragma unroll
    for (int t = 0; t < 10; ++t) cc[t] = __ldg(&g_c3[t]);

    const long long stride = (long long)gridDim.x * blockDim.x;
    const long long tid    = (long long)blockIdx.x * blockDim.x + threadIdx.x;
    const long long pairs  = rows >> 1;

    for (long long p = tid; p < pairs; p += stride) {
        const float4* xp = (const float4*)(x + p * 20);  // p*80 bytes, 16B-aligned
        float4 v0 = xp[0], v1 = xp[1], v2 = xp[2], v3 = xp[3], v4 = xp[4];

        float h0[10], h1[10];
        h0[0] = v0.x; h0[1] = v0.y; h0[2] = v0.z; h0[3] = v0.w;
        h0[4] = v1.x; h0[5] = v1.y; h0[6] = v1.z; h0[7] = v1.w;
        h0[8] = v2.x; h0[9] = v2.y;
        h1[0] = v2.z; h1[1] = v2.w;
        h1[2] = v3.x; h1[3] = v3.y; h1[4] = v3.z; h1[5] = v3.w;
        h1[6] = v4.x; h1[7] = v4.y; h1[8] = v4.z; h1[9] = v4.w;

        float o0[10], o1[10];
        #pragma unroll
        for (int j = 0; j < 10; ++j) {
            float a = cc[j], bsum = cc[j];
            #pragma unroll
            for (int k = 0; k < 10; ++k) {
                a    += h0[k] * m[j * 10 + k];
                bsum += h1[k] * m[j * 10 + k];
            }
            o0[j] = a;
            o1[j] = bsum;
        }

        float4* op = (float4*)(out + p * 20);
        float4 s0, s1, s2, s3, s4;
        s0.x = o0[0]; s0.y = o0[1]; s0.z = o0[2]; s0.w = o0[3];
        s1.x = o0[4]; s1.y = o0[5]; s1.z = o0[6]; s1.w = o0[7];
        s2.x = o0[8]; s2.y = o0[9]; s2.z = o1[0]; s2.w = o1[1];
        s3.x = o1[2]; s3.y = o1[3]; s3.z = o1[4]; s3.w = o1[5];
        s4.x = o1[6]; s4.y = o1[7]; s4.z = o1[8]; s4.w = o1[9];
        op[0] = s0; op[1] = s1; op[2] = s2; op[3] = s3; op[4] = s4;
    }

    // Odd-row tail (BATCH is even, but stay safe).
    for (long long r = pairs * 2 + tid; r < rows; r += stride) {
        const float* xr = x + r * 10;
        float h[10];
        #pragma unroll
        for (int k = 0; k < 10; ++k) h[k] = xr[k];
        float* orow = out + r * 10;
        #pragma unroll
        for (int j = 0; j < 10; ++j) {
            float a = cc[j];
            #pragma unroll
            for (int k = 0; k < 10; ++k) a += h[k] * m[j * 10 + k];
            orow[j] = a;
        }
    }
}

extern "C" void kernel_launch(void* const* d_in, const int* in_sizes, int n_in,
                              void* d_out, int out_size) {
    // Identify inputs robustly by element count: x=BATCH*10, Ws=1000*100, bs=1000*10.
    const float* x  = nullptr;
    const float* Ws = nullptr;
    const float* bs = nullptr;
    long long x_elems = 0;
    for (int i = 0; i < n_in; ++i) {
        if (in_sizes[i] == 1000 * 100) {
            Ws = (const float*)d_in[i];
        } else if (in_sizes[i] == 1000 * 10) {
            bs = (const float*)d_in[i];
        } else {
            x = (const float*)d_in[i];
            x_elems = in_sizes[i];
        }
    }
    const long long rows = x_elems / 10;

    float *M1, *c1, *M2, *c2, *M3, *c3;
    cudaGetSymbolAddress((void**)&M1, g_M1);
    cudaGetSymbolAddress((void**)&c1, g_c1);
    cudaGetSymbolAddress((void**)&M2, g_M2);
    cudaGetSymbolAddress((void**)&c2, g_c2);
    cudaGetSymbolAddress((void**)&M3, g_M3);
    cudaGetSymbolAddress((void**)&c3, g_c3);

    // Compose 1000 affines -> 1 affine via 3-level tree (10 each).
    fold_kernel<10><<<100, 128>>>(Ws, bs, M1, c1);
    fold_kernel<10><<<10, 128>>>(M1, c1, M2, c2);
    fold_kernel<10><<<1, 128>>>(M2, c2, M3, c3);

    // Streaming apply, persistent grid (~3 CTAs/SM at ~160 regs/thread).
    apply_kernel<<<444, 128>>>(x, (float*)d_out, rows);
}